// round 9
// baseline (speedup 1.0000x reference)
#include <cuda_runtime.h>
#include <math.h>

#define BB 64
#define HH 14
#define WW 14
#define CC 32
#define OO 10
#define NN (HH*WW*CC)          /* 6272 */
#define HALF_S 98
#define NBLK 128               /* persistent blocks */
#define GSZ 4                  /* points per staged group */
#define NGRP2 25               /* 24 groups of 4 + tail of 2 */
#define NB 49                  /* batches of 2 points */
#define EPSV 1e-9f
#define LOG2E 1.4426950408889634f
#define LN2PI 1.8378770664093453f

/* double-buffered cross-block partials: [parity][half][b][o][33] */
__device__ float g_part[2][2*BB*OO*33];
__device__ unsigned int g_ctr;
__device__ unsigned int g_epoch;

typedef unsigned long long u64;
__device__ __forceinline__ u64 pk2(float lo, float hi){ u64 r; asm("mov.b64 %0,{%1,%2};" :"=l"(r):"f"(lo),"f"(hi)); return r; }
__device__ __forceinline__ void upk2(u64 a, float& lo, float& hi){ asm("mov.b64 {%0,%1},%2;":"=f"(lo),"=f"(hi):"l"(a)); }
__device__ __forceinline__ u64 fma2(u64 a,u64 b,u64 c){ u64 r; asm("fma.rn.f32x2 %0,%1,%2,%3;":"=l"(r):"l"(a),"l"(b),"l"(c)); return r; }
__device__ __forceinline__ u64 add2(u64 a,u64 b){ u64 r; asm("add.rn.f32x2 %0,%1,%2;":"=l"(r):"l"(a),"l"(b)); return r; }
__device__ __forceinline__ u64 mul2(u64 a,u64 b){ u64 r; asm("mul.rn.f32x2 %0,%1,%2;":"=l"(r):"l"(a),"l"(b)); return r; }
__device__ __forceinline__ float ex2f(float x){ float r; asm("ex2.approx.f32 %0,%1;":"=f"(r):"f"(x)); return r; }
__device__ __forceinline__ float rcpf(float x){ float r; asm("rcp.approx.f32 %0,%1;":"=f"(r):"f"(x)); return r; }

struct Shm {
    float  act [HALF_S*CC];          /* 12544 B */
    float  sbuf[2][GSZ*CC*18];       /* 2 x 9216 B pair-swizzled pose */
    u64    offs[HALF_S];
    float  lgb [2][2*OO*CC];         /* logit exchange, [par][pt][o][c] */
    float  rrb [2][2*OO*CC];         /* normalized rr,   [par][pt][o][c] */
    u64    A2pk[OO*8];
    u64    Mpk [OO*8];
    float  Mu  [OO*16];
    float  C0  [OO];
    unsigned e0;
};

__device__ __forceinline__ void grid_barrier(unsigned target_epoch){
    __threadfence();
    __syncthreads();
    if (threadIdx.x == 0 && threadIdx.y == 0){
        unsigned a = atomicAdd(&g_ctr, 1u);
        if (a == NBLK-1u){
            atomicExch(&g_ctr, 0u);
            __threadfence();
            atomicAdd(&g_epoch, 1u);
        } else {
            while ((int)(*(volatile unsigned*)&g_epoch) - (int)target_epoch < 0) { }
        }
    }
    __syncthreads();
}

__device__ __forceinline__ void ldg_rows(const float4* pb4, int g, int t,
                                         float4& p0, float4& p1, float4& p2, float4& p3){
    const float4* s = pb4 + ((size_t)g*GSZ*CC + t)*4;
    p0 = s[0]; p1 = s[1]; p2 = s[2]; p3 = s[3];
}
__device__ __forceinline__ void sts_row(float* slotbuf, int t,
                                        const float4& p0, const float4& p1,
                                        const float4& p2, const float4& p3){
    float2* sb2 = (float2*)&slotbuf[t*18];
    sb2[0] = make_float2(p0.x, p1.x);
    sb2[1] = make_float2(p0.y, p1.y);
    sb2[2] = make_float2(p0.z, p1.z);
    sb2[3] = make_float2(p0.w, p1.w);
    sb2[4] = make_float2(p2.x, p3.x);
    sb2[5] = make_float2(p2.y, p3.y);
    sb2[6] = make_float2(p2.z, p3.z);
    sb2[7] = make_float2(p2.w, p3.w);
}

/* votes -> (centered) u for one point from staged pose */
template<int CENTER>
__device__ __forceinline__ void votes_u(
    const float* slotbuf, int row, int c,
    const u64 wpk[4][4], const u64 nMU[2][4], u64 uo[2][4], u64 offpk)
{
    const u64* q = (const u64*)slotbuf + ((size_t)row*CC + c)*9;
    const u64 j0a=q[0], j1a=q[1], j2a=q[2], j3a=q[3];
    const u64 j0b=q[4], j1b=q[5], j2b=q[6], j3b=q[7];
#pragma unroll
    for (int k = 0; k < 4; k++){
        u64 a0, a1;
        if (CENTER){ a0 = fma2(j0a, wpk[0][k], nMU[0][k]);
                     a1 = fma2(j0b, wpk[0][k], nMU[1][k]); }
        else       { a0 = mul2(j0a, wpk[0][k]);
                     a1 = mul2(j0b, wpk[0][k]); }
        a0 = fma2(j1a, wpk[1][k], a0);
        a1 = fma2(j1b, wpk[1][k], a1);
        a0 = fma2(j2a, wpk[2][k], a0);
        a1 = fma2(j2b, wpk[2][k], a1);
        a0 = fma2(j3a, wpk[3][k], a0);
        a1 = fma2(j3b, wpk[3][k], a1);
        uo[0][k] = a0; uo[1][k] = a1;
    }
    uo[0][3] = add2(uo[0][3], offpk);
}

__device__ __forceinline__ float logit_of(const u64 uo[2][4], const u64 A2[2][4], float C0){
    u64 q2, l2;
    q2 = mul2(uo[0][0], uo[0][0]); l2 = mul2(q2, A2[0][0]);
    q2 = mul2(uo[0][1], uo[0][1]); l2 = fma2(q2, A2[0][1], l2);
    q2 = mul2(uo[0][2], uo[0][2]); l2 = fma2(q2, A2[0][2], l2);
    q2 = mul2(uo[0][3], uo[0][3]); l2 = fma2(q2, A2[0][3], l2);
    q2 = mul2(uo[1][0], uo[1][0]); l2 = fma2(q2, A2[1][0], l2);
    q2 = mul2(uo[1][1], uo[1][1]); l2 = fma2(q2, A2[1][1], l2);
    q2 = mul2(uo[1][2], uo[1][2]); l2 = fma2(q2, A2[1][2], l2);
    q2 = mul2(uo[1][3], uo[1][3]); l2 = fma2(q2, A2[1][3], l2);
    float x, y; upk2(l2, x, y);
    return C0 + (x + y);
}

__device__ __forceinline__ void accum(float rp, const u64 uo[2][4],
                                      float& S0, u64 S1[2][4], u64 S2[2][4]){
    S0 += rp;
    const u64 rk = pk2(rp, rp);
#pragma unroll
    for (int p = 0; p < 2; p++)
#pragma unroll
    for (int k = 0; k < 4; k++){
        const u64 ru = mul2(rk, uo[p][k]);
        S1[p][k] = add2(S1[p][k], ru);
        S2[p][k] = fma2(ru, uo[p][k], S2[p][k]);
    }
}

__device__ __forceinline__ void reduce_store(float* gp, float S0, const u64 S1[2][4],
                                             const u64 S2[2][4], int c){
    float f[33];
#pragma unroll
    for (int p = 0; p < 2; p++)
#pragma unroll
    for (int k = 0; k < 4; k++){
        upk2(S1[p][k], f[p*8+k],    f[p*8+4+k]);
        upk2(S2[p][k], f[16+p*8+k], f[16+p*8+4+k]);
    }
    f[32] = S0;
#pragma unroll
    for (int off = 16; off > 0; off >>= 1){
#pragma unroll
        for (int i = 0; i < 33; i++)
            f[i] += __shfl_down_sync(0xffffffffu, f[i], off);
    }
    if (c == 0){
#pragma unroll
        for (int i = 0; i < 33; i++) gp[i] = f[i];
    }
}

/* ---------------- IT == 0 pass: uniform rr = 0.1, no softmax ---------------- */
__device__ __forceinline__ void stats_pass_zero(
    const float* __restrict__ pose_blk, Shm* sh,
    const u64 wpk[4][4], int c, int o, float* gp)
{
    u64 S1[2][4], S2[2][4]; float S0 = 0.f;
#pragma unroll
    for (int p = 0; p < 2; p++)
#pragma unroll
    for (int k = 0; k < 4; k++){ S1[p][k] = 0ull; S2[p][k] = 0ull; }

    const int t = o*32 + c;
    const float4* pb4 = (const float4*)pose_blk;
    u64 dummy[2][4];

    float4 pr0, pr1, pr2, pr3;
    if (t < GSZ*CC){
        ldg_rows(pb4, 0, t, pr0, pr1, pr2, pr3);
        sts_row(sh->sbuf[0], t, pr0, pr1, pr2, pr3);
        ldg_rows(pb4, 1, t, pr0, pr1, pr2, pr3);
    }
    __syncthreads();

    for (int g = 0; g < NGRP2; g++){
        const int pts = (g == NGRP2-1) ? 2 : GSZ;
        const float* slot = sh->sbuf[g & 1];
#pragma unroll 4
        for (int lp = 0; lp < pts; lp++){
            u64 uo[2][4];
            votes_u<0>(slot, lp, c, wpk, dummy, uo, sh->offs[g*GSZ + lp]);
            const float rp = 0.1f * sh->act[(g*GSZ + lp)*CC + c];
            accum(rp, uo, S0, S1, S2);
        }
        const int gn = g + 1;
        if (gn < NGRP2){
            const int rows = (gn == NGRP2-1) ? 2*CC : GSZ*CC;
            if (t < rows) sts_row(sh->sbuf[gn & 1], t, pr0, pr1, pr2, pr3);
            const int gp2 = gn + 1;
            if (gp2 < NGRP2){
                const int prow = (gp2 == NGRP2-1) ? 2*CC : GSZ*CC;
                if (t < prow) ldg_rows(pb4, gp2, t, pr0, pr1, pr2, pr3);
            }
        }
        __syncthreads();
    }
    reduce_store(gp, S0, S1, S2, c);
}

/* ------------- IT > 0 pass: single-sync pipelined softmax routing ----------- */
__device__ __forceinline__ void stats_pass_soft(
    const float* __restrict__ pose_blk, Shm* sh,
    const u64 wpk[4][4], int c, int o, float* gp)
{
    u64 A2[2][4], nMU[2][4];
    const float C0 = sh->C0[o];
#pragma unroll
    for (int p = 0; p < 2; p++)
#pragma unroll
    for (int k = 0; k < 4; k++){
        A2[p][k]  = sh->A2pk[o*8 + p*4 + k];
        nMU[p][k] = sh->Mpk [o*8 + p*4 + k];
    }

    u64 S1[2][4], S2[2][4]; float S0 = 0.f;
#pragma unroll
    for (int p = 0; p < 2; p++)
#pragma unroll
    for (int k = 0; k < 4; k++){ S1[p][k] = 0ull; S2[p][k] = 0ull; }

    const int t = o*32 + c;
    const float4* pb4 = (const float4*)pose_blk;

    float4 pr0, pr1, pr2, pr3;
    if (t < GSZ*CC){
        ldg_rows(pb4, 0, t, pr0, pr1, pr2, pr3);
        sts_row(sh->sbuf[0], t, pr0, pr1, pr2, pr3);
        ldg_rows(pb4, 1, t, pr0, pr1, pr2, pr3);
    }
    __syncthreads();

    u64 ub[2][2][2][4];    /* [batch parity][pt][p][k] */

    /* sweep1 of batch 0 */
    votes_u<1>(sh->sbuf[0], 0, c, wpk, nMU, ub[0][0], sh->offs[0]);
    sh->lgb[0][0*OO*CC + o*CC + c] = logit_of(ub[0][0], A2, C0);
    votes_u<1>(sh->sbuf[0], 1, c, wpk, nMU, ub[0][1], sh->offs[1]);
    sh->lgb[0][1*OO*CC + o*CC + c] = logit_of(ub[0][1], A2, C0);
    __syncthreads();

    for (int k = 0; k < NB; k++){
        const int par = k & 1;

        /* rotating reducers: warps r (pt0) and r+1 (pt1), r always even */
        const int r = (2*k) % 10;
        const int mypt = (o == r) ? 0 : ((o == r + 1) ? 1 : -1);
        if (mypt >= 0){
            const float* lb = &sh->lgb[par][mypt*OO*CC + c];
            float lv[OO];
#pragma unroll
            for (int oo = 0; oo < OO; oo++) lv[oo] = lb[oo*CC];
            const float m01 = fmaxf(lv[0], lv[1]);
            const float m23 = fmaxf(lv[2], lv[3]);
            const float m45 = fmaxf(lv[4], lv[5]);
            const float m67 = fmaxf(lv[6], lv[7]);
            const float m89 = fmaxf(lv[8], lv[9]);
            const float m = fmaxf(fmaxf(fmaxf(m01, m23), fmaxf(m45, m67)), m89);
            float ex[OO];
#pragma unroll
            for (int oo = 0; oo < OO; oo++) ex[oo] = ex2f(lv[oo] - m);
            const float s = (((ex[0]+ex[1])+(ex[2]+ex[3])) + ((ex[4]+ex[5])+(ex[6]+ex[7]))) + (ex[8]+ex[9]);
            const float inv = rcpf(s);
            float* rb = &sh->rrb[par][mypt*OO*CC + c];
#pragma unroll
            for (int oo = 0; oo < OO; oo++) rb[oo*CC] = ex[oo]*inv;
        }

        /* sweep2 of batch k-1 (rrb[k-1] & lgb ordering published by prev sync) */
        if (k > 0){
            const int pm = (k-1) & 1;
#pragma unroll
            for (int pt = 0; pt < 2; pt++){
                const float rr = sh->rrb[pm][pt*OO*CC + o*CC + c];
                const float rp = rr * sh->act[(2*(k-1)+pt)*CC + c];
                accum(rp, ub[pm][pt], S0, S1, S2);
            }
        }

        /* sweep1 of batch k+1 */
        if (k + 1 < NB){
            const int m1 = k + 1, p1 = m1 & 1;
            const float* slot = sh->sbuf[(m1 >> 1) & 1];
            const int poff = (m1 & 1) * 2;
            votes_u<1>(slot, poff+0, c, wpk, nMU, ub[p1][0], sh->offs[2*m1]);
            sh->lgb[p1][0*OO*CC + o*CC + c] = logit_of(ub[p1][0], A2, C0);
            votes_u<1>(slot, poff+1, c, wpk, nMU, ub[p1][1], sh->offs[2*m1+1]);
            sh->lgb[p1][1*OO*CC + o*CC + c] = logit_of(ub[p1][1], A2, C0);
        }

        /* staged-group STS/LDG cadence: stage group g+1 when k+1 is last batch of g */
        if ((k & 1) == 0){
            const int gn = (k >> 1) + 1;
            if (gn < NGRP2){
                const int rows = (gn == NGRP2-1) ? 2*CC : GSZ*CC;
                if (t < rows) sts_row(sh->sbuf[gn & 1], t, pr0, pr1, pr2, pr3);
                const int gp2 = gn + 1;
                if (gp2 < NGRP2){
                    const int prow = (gp2 == NGRP2-1) ? 2*CC : GSZ*CC;
                    if (t < prow) ldg_rows(pb4, gp2, t, pr0, pr1, pr2, pr3);
                }
            }
        }
        __syncthreads();
    }

    /* epilogue: sweep2 of last batch */
    {
        const int pm = (NB-1) & 1;
#pragma unroll
        for (int pt = 0; pt < 2; pt++){
            const float rr = sh->rrb[pm][pt*OO*CC + o*CC + c];
            const float rp = rr * sh->act[(2*(NB-1)+pt)*CC + c];
            accum(rp, ub[pm][pt], S0, S1, S2);
        }
    }
    reduce_store(gp, S0, S1, S2, c);
}

__device__ __forceinline__ void block_finalize(
    int it, int b, int tid, Shm* sh,
    const float* __restrict__ beta_a, const float* __restrict__ beta_u,
    float* __restrict__ out)
{
    if (tid < 160){
        const int o = tid >> 4, d = tid & 15;
        const float* buf = g_part[it & 1];
        const float* gp0 = &buf[((0*BB + b)*OO + o)*33];
        const float* gp1 = &buf[((1*BB + b)*OO + o)*33];
        const float T1 = __ldcg(gp0 + d)      + __ldcg(gp1 + d);
        const float T2 = __ldcg(gp0 + 16 + d) + __ldcg(gp1 + 16 + d);
        const float S0 = __ldcg(gp0 + 32)     + __ldcg(gp1 + 32);
        const float mu_prev = (it == 0) ? 0.f : sh->Mu[o*16 + d];

        /* exact shifted-moment identity in fp64 (cancellation-safe) */
        const double S0d = (double)S0;
        const double rsd = S0d + (double)EPSV;
        const double S1d = (double)T1 + (double)mu_prev * S0d;
        const double mud = S1d / rsd;
        const double e   = mud - (double)mu_prev;
        double varnum = (double)T2 - 2.0*e*(double)T1 + e*e*S0d;
        if (varnum < 0.0) varnum = 0.0;
        const double vard = varnum / rsd + (double)EPSV;

        const float mu   = (float)mud;
        const float var  = (float)vard;
        const float lvar = logf(var);
        const float iv   = 1.0f/var;
        const float rs   = (float)rsd;

        float r1 = lvar;
#pragma unroll
        for (int m = 8; m > 0; m >>= 1)
            r1 += __shfl_xor_sync(0xffffffffu, r1, m);

        const float cost     = rs * (16.0f*beta_u[o] + 0.5f*r1);
        const float inv_temp = 1.0f + (float)it;
        const float z        = inv_temp * (beta_a[o] - cost);
        const float actv     = 1.0f / (1.0f + expf(-z));

        if (it < 2){
            const int p = d >> 3, hi = (d >> 2) & 1, k = d & 3;
            ((float*)&sh->A2pk[o*8 + p*4 + k])[hi] = -0.5f*iv*LOG2E;
            ((float*)&sh->Mpk [o*8 + p*4 + k])[hi] = -mu;
            sh->Mu[o*16 + d] = mu;
            if (d == 0)
                sh->C0[o] = (logf(actv + EPSV) - 0.5f*(16.0f*LN2PI + r1)) * LOG2E;
        } else {
            out[(b*OO + o)*16 + d] = mu;
            if (d == 0) out[BB*OO*16 + b*OO + o] = actv;
        }
    }
    __syncthreads();
}

__global__ __launch_bounds__(320)
void fccaps_kernel(const float* __restrict__ pose,
                   const float* __restrict__ act,
                   const float* __restrict__ wmat,
                   const float* __restrict__ beta_a,
                   const float* __restrict__ beta_u,
                   float* __restrict__ out)
{
    __shared__ Shm sh;

    const int c   = threadIdx.x;
    const int o   = threadIdx.y;
    const int tid = o*32 + c;
    const int b    = blockIdx.x >> 1;
    const int half = blockIdx.x & 1;
    const int s0   = half * HALF_S;

    for (int i = tid; i < HALF_S*CC; i += 320)
        sh.act[i] = act[(size_t)b*NN + (size_t)s0*CC + i];
    if (tid < HALF_S){
        const int s = s0 + tid;
        sh.offs[tid] = pk2(((s % WW) + 0.5f)*(1.0f/WW),
                           ((s / WW) + 0.5f)*(1.0f/HH));
    }
    if (tid == 0) sh.e0 = *(volatile unsigned*)&g_epoch;

    u64 wpk[4][4];
#pragma unroll
    for (int j = 0; j < 4; j++)
#pragma unroll
    for (int k = 0; k < 4; k++){
        const float wv = wmat[((size_t)(c*OO + o))*16 + j*4 + k];
        wpk[j][k] = pk2(wv, wv);
    }
    __syncthreads();
    const unsigned e0 = sh.e0;

    const float* pose_blk = pose + ((size_t)b*NN + (size_t)s0*CC)*16;
    const size_t gpi = (((size_t)half*BB + b)*OO + o)*33;

    stats_pass_zero(pose_blk, &sh, wpk, c, o, &g_part[0][gpi]);
    grid_barrier(e0 + 1);
    block_finalize(0, b, tid, &sh, beta_a, beta_u, out);

    stats_pass_soft(pose_blk, &sh, wpk, c, o, &g_part[1][gpi]);
    grid_barrier(e0 + 2);
    block_finalize(1, b, tid, &sh, beta_a, beta_u, out);

    stats_pass_soft(pose_blk, &sh, wpk, c, o, &g_part[0][gpi]);
    grid_barrier(e0 + 3);
    if (half == 0)
        block_finalize(2, b, tid, &sh, beta_a, beta_u, out);
}

extern "C" void kernel_launch(void* const* d_in, const int* in_sizes, int n_in,
                              void* d_out, int out_size)
{
    const float* pose = (const float*)d_in[0];  // (B,H,W,C,16)
    const float* actv = (const float*)d_in[1];  // (B,H,W,C,1)
    const float* wmat = (const float*)d_in[2];  // (C,O,4,4)
    const float* ba   = (const float*)d_in[3];  // (1,1,O,1)
    const float* bu   = (const float*)d_in[4];  // (1,1,O,1)
    float* out = (float*)d_out;                 // pose(B,O,16) then act(B,O)

    dim3 blk(32, 10);
    fccaps_kernel<<<NBLK, blk>>>(pose, actv, wmat, ba, bu, out);
}

// round 10
// speedup vs baseline: 1.2075x; 1.2075x over previous
#include <cuda_runtime.h>
#include <math.h>

#define BB 64
#define HH 14
#define WW 14
#define CC 32
#define OO 10
#define NN (HH*WW*CC)          /* 6272 */
#define HALF_S 98
#define NBLK 128               /* persistent blocks */
#define GSZ 4                  /* points per staged group */
#define NGRP2 25               /* 24 groups of 4 + tail of 2 */
#define NB 49                  /* batches of 2 points */
#define EPSV 1e-9f
#define LOG2E 1.4426950408889634f
#define LN2PI 1.8378770664093453f

/* double-buffered cross-block partials: [parity][half][b][o][33] */
__device__ float g_part[2][2*BB*OO*33];
__device__ unsigned int g_ctr;
__device__ unsigned int g_epoch;

typedef unsigned long long u64;
__device__ __forceinline__ u64 pk2(float lo, float hi){ u64 r; asm("mov.b64 %0,{%1,%2};" :"=l"(r):"f"(lo),"f"(hi)); return r; }
__device__ __forceinline__ void upk2(u64 a, float& lo, float& hi){ asm("mov.b64 {%0,%1},%2;":"=f"(lo),"=f"(hi):"l"(a)); }
__device__ __forceinline__ u64 fma2(u64 a,u64 b,u64 c){ u64 r; asm("fma.rn.f32x2 %0,%1,%2,%3;":"=l"(r):"l"(a),"l"(b),"l"(c)); return r; }
__device__ __forceinline__ u64 add2(u64 a,u64 b){ u64 r; asm("add.rn.f32x2 %0,%1,%2;":"=l"(r):"l"(a),"l"(b)); return r; }
__device__ __forceinline__ u64 mul2(u64 a,u64 b){ u64 r; asm("mul.rn.f32x2 %0,%1,%2;":"=l"(r):"l"(a),"l"(b)); return r; }
__device__ __forceinline__ float ex2f(float x){ float r; asm("ex2.approx.f32 %0,%1;":"=f"(r):"f"(x)); return r; }
__device__ __forceinline__ float rcpf(float x){ float r; asm("rcp.approx.f32 %0,%1;":"=f"(r):"f"(x)); return r; }

struct Shm {
    float  act [HALF_S*CC];          /* 12544 B */
    float  sbuf[2][GSZ*CC*18];       /* 2 x 9216 B pair-swizzled pose */
    u64    offs[HALF_S];
    float  lgb [2][2*OO*CC];         /* logit exchange, [par][pt][o][c] */
    float  rrb [2][2*OO*CC];         /* normalized rr,   [par][pt][o][c] */
    u64    A2pk[OO*8];
    u64    Mpk [OO*8];
    float  Mu  [OO*16];
    float  C0  [OO];
    unsigned e0;
};

__device__ __forceinline__ void grid_barrier(unsigned target_epoch){
    __threadfence();
    __syncthreads();
    if (threadIdx.x == 0 && threadIdx.y == 0){
        unsigned a = atomicAdd(&g_ctr, 1u);
        if (a == NBLK-1u){
            atomicExch(&g_ctr, 0u);
            __threadfence();
            atomicAdd(&g_epoch, 1u);
        } else {
            while ((int)(*(volatile unsigned*)&g_epoch) - (int)target_epoch < 0) { }
        }
    }
    __syncthreads();
}

__device__ __forceinline__ void ldg_rows(const float4* pb4, int g, int t,
                                         float4& p0, float4& p1, float4& p2, float4& p3){
    const float4* s = pb4 + ((size_t)g*GSZ*CC + t)*4;
    p0 = s[0]; p1 = s[1]; p2 = s[2]; p3 = s[3];
}
__device__ __forceinline__ void sts_row(float* slotbuf, int t,
                                        const float4& p0, const float4& p1,
                                        const float4& p2, const float4& p3){
    float2* sb2 = (float2*)&slotbuf[t*18];
    sb2[0] = make_float2(p0.x, p1.x);
    sb2[1] = make_float2(p0.y, p1.y);
    sb2[2] = make_float2(p0.z, p1.z);
    sb2[3] = make_float2(p0.w, p1.w);
    sb2[4] = make_float2(p2.x, p3.x);
    sb2[5] = make_float2(p2.y, p3.y);
    sb2[6] = make_float2(p2.z, p3.z);
    sb2[7] = make_float2(p2.w, p3.w);
}

/* votes -> (centered) u for one point from staged pose */
template<int CENTER>
__device__ __forceinline__ void votes_u(
    const float* slotbuf, int row, int c,
    const u64 wpk[4][4], const u64 nMU[2][4], u64 uo[2][4], u64 offpk)
{
    const u64* q = (const u64*)slotbuf + ((size_t)row*CC + c)*9;
    const u64 j0a=q[0], j1a=q[1], j2a=q[2], j3a=q[3];
    const u64 j0b=q[4], j1b=q[5], j2b=q[6], j3b=q[7];
#pragma unroll
    for (int k = 0; k < 4; k++){
        u64 a0, a1;
        if (CENTER){ a0 = fma2(j0a, wpk[0][k], nMU[0][k]);
                     a1 = fma2(j0b, wpk[0][k], nMU[1][k]); }
        else       { a0 = mul2(j0a, wpk[0][k]);
                     a1 = mul2(j0b, wpk[0][k]); }
        a0 = fma2(j1a, wpk[1][k], a0);
        a1 = fma2(j1b, wpk[1][k], a1);
        a0 = fma2(j2a, wpk[2][k], a0);
        a1 = fma2(j2b, wpk[2][k], a1);
        a0 = fma2(j3a, wpk[3][k], a0);
        a1 = fma2(j3b, wpk[3][k], a1);
        uo[0][k] = a0; uo[1][k] = a1;
    }
    uo[0][3] = add2(uo[0][3], offpk);
}

__device__ __forceinline__ float logit_of(const u64 uo[2][4], const u64 A2[2][4], float C0){
    u64 q2, l2;
    q2 = mul2(uo[0][0], uo[0][0]); l2 = mul2(q2, A2[0][0]);
    q2 = mul2(uo[0][1], uo[0][1]); l2 = fma2(q2, A2[0][1], l2);
    q2 = mul2(uo[0][2], uo[0][2]); l2 = fma2(q2, A2[0][2], l2);
    q2 = mul2(uo[0][3], uo[0][3]); l2 = fma2(q2, A2[0][3], l2);
    q2 = mul2(uo[1][0], uo[1][0]); l2 = fma2(q2, A2[1][0], l2);
    q2 = mul2(uo[1][1], uo[1][1]); l2 = fma2(q2, A2[1][1], l2);
    q2 = mul2(uo[1][2], uo[1][2]); l2 = fma2(q2, A2[1][2], l2);
    q2 = mul2(uo[1][3], uo[1][3]); l2 = fma2(q2, A2[1][3], l2);
    float x, y; upk2(l2, x, y);
    return C0 + (x + y);
}

__device__ __forceinline__ void accum(float rp, const u64 uo[2][4],
                                      float& S0, u64 S1[2][4], u64 S2[2][4]){
    S0 += rp;
    const u64 rk = pk2(rp, rp);
#pragma unroll
    for (int p = 0; p < 2; p++)
#pragma unroll
    for (int k = 0; k < 4; k++){
        const u64 ru = mul2(rk, uo[p][k]);
        S1[p][k] = add2(S1[p][k], ru);
        S2[p][k] = fma2(ru, uo[p][k], S2[p][k]);
    }
}

__device__ __forceinline__ void reduce_store(float* gp, float S0, const u64 S1[2][4],
                                             const u64 S2[2][4], int c){
    float f[33];
#pragma unroll
    for (int p = 0; p < 2; p++)
#pragma unroll
    for (int k = 0; k < 4; k++){
        upk2(S1[p][k], f[p*8+k],    f[p*8+4+k]);
        upk2(S2[p][k], f[16+p*8+k], f[16+p*8+4+k]);
    }
    f[32] = S0;
#pragma unroll
    for (int off = 16; off > 0; off >>= 1){
#pragma unroll
        for (int i = 0; i < 33; i++)
            f[i] += __shfl_down_sync(0xffffffffu, f[i], off);
    }
    if (c == 0){
#pragma unroll
        for (int i = 0; i < 33; i++) gp[i] = f[i];
    }
}

/* ---------------- IT == 0 pass: uniform rr = 0.1, no softmax ---------------- */
__device__ __forceinline__ void stats_pass_zero(
    const float* __restrict__ pose_blk, Shm* sh,
    const u64 wpk[4][4], int c, int o, float* gp)
{
    u64 S1[2][4], S2[2][4]; float S0 = 0.f;
#pragma unroll
    for (int p = 0; p < 2; p++)
#pragma unroll
    for (int k = 0; k < 4; k++){ S1[p][k] = 0ull; S2[p][k] = 0ull; }

    const int t = o*32 + c;
    const float4* pb4 = (const float4*)pose_blk;
    u64 dummy[2][4];

    float4 pr0, pr1, pr2, pr3;
    if (t < GSZ*CC){
        ldg_rows(pb4, 0, t, pr0, pr1, pr2, pr3);
        sts_row(sh->sbuf[0], t, pr0, pr1, pr2, pr3);
        ldg_rows(pb4, 1, t, pr0, pr1, pr2, pr3);
    }
    __syncthreads();

    for (int g = 0; g < NGRP2; g++){
        const int pts = (g == NGRP2-1) ? 2 : GSZ;
        const float* slot = sh->sbuf[g & 1];
#pragma unroll 4
        for (int lp = 0; lp < pts; lp++){
            u64 uo[2][4];
            votes_u<0>(slot, lp, c, wpk, dummy, uo, sh->offs[g*GSZ + lp]);
            const float rp = 0.1f * sh->act[(g*GSZ + lp)*CC + c];
            accum(rp, uo, S0, S1, S2);
        }
        const int gn = g + 1;
        if (gn < NGRP2){
            const int rows = (gn == NGRP2-1) ? 2*CC : GSZ*CC;
            if (t < rows) sts_row(sh->sbuf[gn & 1], t, pr0, pr1, pr2, pr3);
            const int gp2 = gn + 1;
            if (gp2 < NGRP2){
                const int prow = (gp2 == NGRP2-1) ? 2*CC : GSZ*CC;
                if (t < prow) ldg_rows(pb4, gp2, t, pr0, pr1, pr2, pr3);
            }
        }
        __syncthreads();
    }
    reduce_store(gp, S0, S1, S2, c);
}

/* One pipeline step for batch k (parity resolved by the CALLER via pointer /
   array arguments — all indexing below is static):
   - reducers (warps r, r+1) softmax lgb_cur -> rrb_cur
   - sweep2 of batch k-1 reading rr_prev + uOther (holds batch k-1)
   - sweep1 of batch k+1 writing uOther + lg_next
   poff_next = ((k+1)&1)*2, compile-time at each call site. */
__device__ __forceinline__ void pipe_step(
    int k, int r, Shm* sh, int c, int o,
    const float* lgb_cur, float* rr_cur, float* lg_next, const float* rr_prev,
    int poff_next,
    const u64 wpk[4][4], const u64 A2[2][4], const u64 nMU[2][4], float C0,
    u64 uOther[2][2][4],
    float& S0, u64 S1[2][4], u64 S2[2][4])
{
    /* rotating reducers */
    const int mypt = (o == r) ? 0 : ((o == r + 1) ? 1 : -1);
    if (mypt >= 0){
        const float* lb = lgb_cur + mypt*OO*CC + c;
        float lv[OO];
#pragma unroll
        for (int oo = 0; oo < OO; oo++) lv[oo] = lb[oo*CC];
        const float m01 = fmaxf(lv[0], lv[1]);
        const float m23 = fmaxf(lv[2], lv[3]);
        const float m45 = fmaxf(lv[4], lv[5]);
        const float m67 = fmaxf(lv[6], lv[7]);
        const float m89 = fmaxf(lv[8], lv[9]);
        const float m = fmaxf(fmaxf(fmaxf(m01, m23), fmaxf(m45, m67)), m89);
        float ex[OO];
#pragma unroll
        for (int oo = 0; oo < OO; oo++) ex[oo] = ex2f(lv[oo] - m);
        const float s = (((ex[0]+ex[1])+(ex[2]+ex[3])) + ((ex[4]+ex[5])+(ex[6]+ex[7]))) + (ex[8]+ex[9]);
        const float inv = rcpf(s);
        float* rb = rr_cur + mypt*OO*CC + c;
#pragma unroll
        for (int oo = 0; oo < OO; oo++) rb[oo*CC] = ex[oo]*inv;
    }

    /* sweep2 of batch k-1 */
    if (k > 0){
#pragma unroll
        for (int pt = 0; pt < 2; pt++){
            const float rr = rr_prev[pt*OO*CC + o*CC + c];
            const float rp = rr * sh->act[(2*(k-1)+pt)*CC + c];
            accum(rp, uOther[pt], S0, S1, S2);
        }
    }

    /* sweep1 of batch k+1 */
    if (k + 1 < NB){
        const float* slot = sh->sbuf[((k+1) >> 1) & 1];
        votes_u<1>(slot, poff_next+0, c, wpk, nMU, uOther[0], sh->offs[2*(k+1)]);
        lg_next[0*OO*CC + o*CC + c] = logit_of(uOther[0], A2, C0);
        votes_u<1>(slot, poff_next+1, c, wpk, nMU, uOther[1], sh->offs[2*(k+1)+1]);
        lg_next[1*OO*CC + o*CC + c] = logit_of(uOther[1], A2, C0);
    }
}

/* ------------- IT > 0 pass: single-sync pipelined softmax routing ----------- */
__device__ __forceinline__ void stats_pass_soft(
    const float* __restrict__ pose_blk, Shm* sh,
    const u64 wpk[4][4], int c, int o, float* gp)
{
    u64 A2[2][4], nMU[2][4];
    const float C0 = sh->C0[o];
#pragma unroll
    for (int p = 0; p < 2; p++)
#pragma unroll
    for (int k = 0; k < 4; k++){
        A2[p][k]  = sh->A2pk[o*8 + p*4 + k];
        nMU[p][k] = sh->Mpk [o*8 + p*4 + k];
    }

    u64 S1[2][4], S2[2][4]; float S0 = 0.f;
#pragma unroll
    for (int p = 0; p < 2; p++)
#pragma unroll
    for (int k = 0; k < 4; k++){ S1[p][k] = 0ull; S2[p][k] = 0ull; }

    const int t = o*32 + c;
    const float4* pb4 = (const float4*)pose_blk;

    float4 pr0, pr1, pr2, pr3;
    if (t < GSZ*CC){
        ldg_rows(pb4, 0, t, pr0, pr1, pr2, pr3);
        sts_row(sh->sbuf[0], t, pr0, pr1, pr2, pr3);
        ldg_rows(pb4, 1, t, pr0, pr1, pr2, pr3);
    }
    __syncthreads();

    /* two statically-named u arrays: uP0 holds even batches, uP1 odd batches */
    u64 uP0[2][2][4], uP1[2][2][4];

    /* prologue: sweep1 of batch 0 (parity 0) */
    votes_u<1>(sh->sbuf[0], 0, c, wpk, nMU, uP0[0], sh->offs[0]);
    sh->lgb[0][0*OO*CC + o*CC + c] = logit_of(uP0[0], A2, C0);
    votes_u<1>(sh->sbuf[0], 1, c, wpk, nMU, uP0[1], sh->offs[1]);
    sh->lgb[0][1*OO*CC + o*CC + c] = logit_of(uP0[1], A2, C0);
    __syncthreads();

    int r = 0;
    for (int kk = 0; kk < NB-1; kk += 2){
        /* --- step kk (parity 0): cur buf0, other parity arrays = uP1 --- */
        pipe_step(kk, r, sh, c, o,
                  sh->lgb[0], sh->rrb[0], sh->lgb[1], sh->rrb[1],
                  /*poff_next=*/2, wpk, A2, nMU, C0, uP1, S0, S1, S2);
        /* staging cadence on even steps */
        {
            const int gn = (kk >> 1) + 1;
            if (gn < NGRP2){
                const int rows = (gn == NGRP2-1) ? 2*CC : GSZ*CC;
                if (t < rows) sts_row(sh->sbuf[gn & 1], t, pr0, pr1, pr2, pr3);
                const int gp2 = gn + 1;
                if (gp2 < NGRP2){
                    const int prow = (gp2 == NGRP2-1) ? 2*CC : GSZ*CC;
                    if (t < prow) ldg_rows(pb4, gp2, t, pr0, pr1, pr2, pr3);
                }
            }
        }
        __syncthreads();
        r = (r + 2 == 10) ? 0 : r + 2;

        /* --- step kk+1 (parity 1): cur buf1, other parity arrays = uP0 --- */
        pipe_step(kk+1, r, sh, c, o,
                  sh->lgb[1], sh->rrb[1], sh->lgb[0], sh->rrb[0],
                  /*poff_next=*/0, wpk, A2, nMU, C0, uP0, S0, S1, S2);
        __syncthreads();
        r = (r + 2 == 10) ? 0 : r + 2;
    }

    /* final step k = NB-1 = 48 (parity 0) */
    pipe_step(NB-1, r, sh, c, o,
              sh->lgb[0], sh->rrb[0], sh->lgb[1], sh->rrb[1],
              2, wpk, A2, nMU, C0, uP1, S0, S1, S2);
    __syncthreads();

    /* epilogue: sweep2 of batch 48 (parity 0, stored in uP0) */
#pragma unroll
    for (int pt = 0; pt < 2; pt++){
        const float rr = sh->rrb[0][pt*OO*CC + o*CC + c];
        const float rp = rr * sh->act[(2*(NB-1)+pt)*CC + c];
        accum(rp, uP0[pt], S0, S1, S2);
    }
    reduce_store(gp, S0, S1, S2, c);
}

__device__ __forceinline__ void block_finalize(
    int it, int b, int tid, Shm* sh,
    const float* __restrict__ beta_a, const float* __restrict__ beta_u,
    float* __restrict__ out)
{
    if (tid < 160){
        const int o = tid >> 4, d = tid & 15;
        const float* buf = g_part[it & 1];
        const float* gp0 = &buf[((0*BB + b)*OO + o)*33];
        const float* gp1 = &buf[((1*BB + b)*OO + o)*33];
        const float T1 = __ldcg(gp0 + d)      + __ldcg(gp1 + d);
        const float T2 = __ldcg(gp0 + 16 + d) + __ldcg(gp1 + 16 + d);
        const float S0 = __ldcg(gp0 + 32)     + __ldcg(gp1 + 32);
        const float mu_prev = (it == 0) ? 0.f : sh->Mu[o*16 + d];

        /* exact shifted-moment identity in fp64 (cancellation-safe) */
        const double S0d = (double)S0;
        const double rsd = S0d + (double)EPSV;
        const double S1d = (double)T1 + (double)mu_prev * S0d;
        const double mud = S1d / rsd;
        const double e   = mud - (double)mu_prev;
        double varnum = (double)T2 - 2.0*e*(double)T1 + e*e*S0d;
        if (varnum < 0.0) varnum = 0.0;
        const double vard = varnum / rsd + (double)EPSV;

        const float mu   = (float)mud;
        const float var  = (float)vard;
        const float lvar = logf(var);
        const float iv   = 1.0f/var;
        const float rs   = (float)rsd;

        float r1 = lvar;
#pragma unroll
        for (int m = 8; m > 0; m >>= 1)
            r1 += __shfl_xor_sync(0xffffffffu, r1, m);

        const float cost     = rs * (16.0f*beta_u[o] + 0.5f*r1);
        const float inv_temp = 1.0f + (float)it;
        const float z        = inv_temp * (beta_a[o] - cost);
        const float actv     = 1.0f / (1.0f + expf(-z));

        if (it < 2){
            const int p = d >> 3, hi = (d >> 2) & 1, k = d & 3;
            ((float*)&sh->A2pk[o*8 + p*4 + k])[hi] = -0.5f*iv*LOG2E;
            ((float*)&sh->Mpk [o*8 + p*4 + k])[hi] = -mu;
            sh->Mu[o*16 + d] = mu;
            if (d == 0)
                sh->C0[o] = (logf(actv + EPSV) - 0.5f*(16.0f*LN2PI + r1)) * LOG2E;
        } else {
            out[(b*OO + o)*16 + d] = mu;
            if (d == 0) out[BB*OO*16 + b*OO + o] = actv;
        }
    }
    __syncthreads();
}

__global__ __launch_bounds__(320)
void fccaps_kernel(const float* __restrict__ pose,
                   const float* __restrict__ act,
                   const float* __restrict__ wmat,
                   const float* __restrict__ beta_a,
                   const float* __restrict__ beta_u,
                   float* __restrict__ out)
{
    __shared__ Shm sh;

    const int c   = threadIdx.x;
    const int o   = threadIdx.y;
    const int tid = o*32 + c;
    const int b    = blockIdx.x >> 1;
    const int half = blockIdx.x & 1;
    const int s0   = half * HALF_S;

    for (int i = tid; i < HALF_S*CC; i += 320)
        sh.act[i] = act[(size_t)b*NN + (size_t)s0*CC + i];
    if (tid < HALF_S){
        const int s = s0 + tid;
        sh.offs[tid] = pk2(((s % WW) + 0.5f)*(1.0f/WW),
                           ((s / WW) + 0.5f)*(1.0f/HH));
    }
    if (tid == 0) sh.e0 = *(volatile unsigned*)&g_epoch;

    u64 wpk[4][4];
#pragma unroll
    for (int j = 0; j < 4; j++)
#pragma unroll
    for (int k = 0; k < 4; k++){
        const float wv = wmat[((size_t)(c*OO + o))*16 + j*4 + k];
        wpk[j][k] = pk2(wv, wv);
    }
    __syncthreads();
    const unsigned e0 = sh.e0;

    const float* pose_blk = pose + ((size_t)b*NN + (size_t)s0*CC)*16;
    const size_t gpi = (((size_t)half*BB + b)*OO + o)*33;

    stats_pass_zero(pose_blk, &sh, wpk, c, o, &g_part[0][gpi]);
    grid_barrier(e0 + 1);
    block_finalize(0, b, tid, &sh, beta_a, beta_u, out);

    stats_pass_soft(pose_blk, &sh, wpk, c, o, &g_part[1][gpi]);
    grid_barrier(e0 + 2);
    block_finalize(1, b, tid, &sh, beta_a, beta_u, out);

    stats_pass_soft(pose_blk, &sh, wpk, c, o, &g_part[0][gpi]);
    grid_barrier(e0 + 3);
    if (half == 0)
        block_finalize(2, b, tid, &sh, beta_a, beta_u, out);
}

extern "C" void kernel_launch(void* const* d_in, const int* in_sizes, int n_in,
                              void* d_out, int out_size)
{
    const float* pose = (const float*)d_in[0];  // (B,H,W,C,16)
    const float* actv = (const float*)d_in[1];  // (B,H,W,C,1)
    const float* wmat = (const float*)d_in[2];  // (C,O,4,4)
    const float* ba   = (const float*)d_in[3];  // (1,1,O,1)
    const float* bu   = (const float*)d_in[4];  // (1,1,O,1)
    float* out = (float*)d_out;                 // pose(B,O,16) then act(B,O)

    dim3 blk(32, 10);
    fccaps_kernel<<<NBLK, blk>>>(pose, actv, wmat, ba, bu, out);
}

// round 13
// speedup vs baseline: 1.3944x; 1.1548x over previous
#include <cuda_runtime.h>
#include <math.h>

#define BB 64
#define HH 14
#define WW 14
#define CC 32
#define OO 10
#define NN (HH*WW*CC)          /* 6272 */
#define HALF_S 98
#define NBLK 128               /* persistent blocks */
#define G 8                    /* points per staged group */
#define NGRP 13                /* 12 groups of 8 + one of 2 */
#define EPSV 1e-9f
#define LOG2E 1.4426950408889634f
#define LN2PI 1.8378770664093453f

/* double-buffered cross-block partials: [parity][half][b][o][33] */
__device__ float g_part[2][2*BB*OO*33];
/* per-block moment stats for factored IT0: [blk][stat][c], 69 stats padded to 72 */
__device__ float g_mst[NBLK][72*CC];
__device__ unsigned int g_ctr;
__device__ unsigned int g_epoch;

typedef unsigned long long u64;
__device__ __forceinline__ u64 pk2(float lo, float hi){ u64 r; asm("mov.b64 %0,{%1,%2};" :"=l"(r):"f"(lo),"f"(hi)); return r; }
__device__ __forceinline__ void upk2(u64 a, float& lo, float& hi){ asm("mov.b64 {%0,%1},%2;":"=f"(lo),"=f"(hi):"l"(a)); }
__device__ __forceinline__ u64 fma2(u64 a,u64 b,u64 c){ u64 r; asm("fma.rn.f32x2 %0,%1,%2,%3;":"=l"(r):"l"(a),"l"(b),"l"(c)); return r; }
__device__ __forceinline__ u64 add2(u64 a,u64 b){ u64 r; asm("add.rn.f32x2 %0,%1,%2;":"=l"(r):"l"(a),"l"(b)); return r; }
__device__ __forceinline__ u64 mul2(u64 a,u64 b){ u64 r; asm("mul.rn.f32x2 %0,%1,%2;":"=l"(r):"l"(a),"l"(b)); return r; }
__device__ __forceinline__ float ex2f(float x){ float r; asm("ex2.approx.f32 %0,%1;":"=f"(r):"f"(x)); return r; }
__device__ __forceinline__ float rcpf(float x){ float r; asm("rcp.approx.f32 %0,%1;":"=f"(r):"f"(x)); return r; }

struct Shm {
    float  act [HALF_S*CC];      /* 12544 B */
    float  sbuf[G*CC*18];        /* 18432 B : pair-swizzled pose, stride 18 */
    u64    offs[HALF_S];         /* packed {w_off, h_off} */
    float  lgb [4*OO*33];        /* logit exchange, 4 points */
    float2 mrs [4*CC];           /* {max, rcp(sum)} per (point, c) */
    u64    A2pk[OO*8];           /* packed -0.5/var*log2e */
    u64    Mpk [OO*8];           /* packed -mu */
    float  Mu  [OO*16];
    float  C0  [OO];
    unsigned e0;
};

__device__ __forceinline__ void grid_barrier(unsigned target_epoch){
    __threadfence();
    __syncthreads();
    if (threadIdx.x == 0 && threadIdx.y == 0){
        unsigned a = atomicAdd(&g_ctr, 1u);
        if (a == NBLK-1u){
            atomicExch(&g_ctr, 0u);
            __threadfence();
            atomicAdd(&g_epoch, 1u);
        } else {
            while ((int)(*(volatile unsigned*)&g_epoch) - (int)target_epoch < 0) { }
        }
    }
    __syncthreads();
}

/* Process a batch of P points (soft iterations): sweep1 (votes->u, logits) with
   pose loads software-pipelined one point ahead, parallel reducers (tree
   max/sum), sweep2 (rr, accumulate). u lives in registers between sweeps. */
template<int P>
__device__ __forceinline__ void process_batch(
    Shm* sh, int gpt0, int lpt0,
    const u64 wpk[4][4], const u64 A2[2][4], const u64 nMU[2][4], float C0,
    int c, int o, float& S0, u64 S1[2][4], u64 S2[2][4])
{
    u64 u[P][2][4];
    float lg[P];
    u64 pp[2][8];                 /* double-buffered pose, 8 u64 per point */

    {
        const u64* s = (const u64*)(sh->sbuf) + ((size_t)lpt0*CC + c)*9;
#pragma unroll
        for (int i = 0; i < 8; i++) pp[0][i] = s[i];
    }

    /* ---- sweep 1: votes -> u (centered), logits ---- */
#pragma unroll
    for (int lp = 0; lp < P; lp++){
        if (lp + 1 < P){
            const u64* s = (const u64*)(sh->sbuf) + ((size_t)(lpt0+lp+1)*CC + c)*9;
#pragma unroll
            for (int i = 0; i < 8; i++) pp[(lp+1)&1][i] = s[i];
        }
        const u64* q = pp[lp&1];
        const u64 j0a = q[0], j1a = q[1], j2a = q[2], j3a = q[3];
        const u64 j0b = q[4], j1b = q[5], j2b = q[6], j3b = q[7];
#pragma unroll
        for (int k = 0; k < 4; k++){
            u64 a0 = fma2(j0a, wpk[0][k], nMU[0][k]);
            u64 a1 = fma2(j0b, wpk[0][k], nMU[1][k]);
            a0 = fma2(j1a, wpk[1][k], a0);
            a1 = fma2(j1b, wpk[1][k], a1);
            a0 = fma2(j2a, wpk[2][k], a0);
            a1 = fma2(j2b, wpk[2][k], a1);
            a0 = fma2(j3a, wpk[3][k], a0);
            a1 = fma2(j3b, wpk[3][k], a1);
            u[lp][0][k] = a0; u[lp][1][k] = a1;
        }
        u[lp][0][3] = add2(u[lp][0][3], sh->offs[gpt0+lp]);

        {
            u64 q2, l2;
            q2 = mul2(u[lp][0][0], u[lp][0][0]); l2 = mul2(q2, A2[0][0]);
            q2 = mul2(u[lp][0][1], u[lp][0][1]); l2 = fma2(q2, A2[0][1], l2);
            q2 = mul2(u[lp][0][2], u[lp][0][2]); l2 = fma2(q2, A2[0][2], l2);
            q2 = mul2(u[lp][0][3], u[lp][0][3]); l2 = fma2(q2, A2[0][3], l2);
            q2 = mul2(u[lp][1][0], u[lp][1][0]); l2 = fma2(q2, A2[1][0], l2);
            q2 = mul2(u[lp][1][1], u[lp][1][1]); l2 = fma2(q2, A2[1][1], l2);
            q2 = mul2(u[lp][1][2], u[lp][1][2]); l2 = fma2(q2, A2[1][2], l2);
            q2 = mul2(u[lp][1][3], u[lp][1][3]); l2 = fma2(q2, A2[1][3], l2);
            float x, y; upk2(l2, x, y);
            lg[lp] = C0 + (x + y);
            sh->lgb[lp*(OO*33) + o*33 + c] = lg[lp];
        }
    }

    /* ---- parallel reducers: warp o reduces point o (tree max/sum) ---- */
    __syncthreads();
    if (o < P){
        const float* lb = sh->lgb + o*(OO*33) + c;
        float lv[OO];
#pragma unroll
        for (int oo = 0; oo < OO; oo++) lv[oo] = lb[oo*33];
        const float m01 = fmaxf(lv[0], lv[1]);
        const float m23 = fmaxf(lv[2], lv[3]);
        const float m45 = fmaxf(lv[4], lv[5]);
        const float m67 = fmaxf(lv[6], lv[7]);
        const float m89 = fmaxf(lv[8], lv[9]);
        const float m = fmaxf(fmaxf(fmaxf(m01, m23), fmaxf(m45, m67)), m89);
        float e0 = ex2f(lv[0]-m), e1 = ex2f(lv[1]-m);
        float e2 = ex2f(lv[2]-m), e3 = ex2f(lv[3]-m);
        float e4 = ex2f(lv[4]-m), e5 = ex2f(lv[5]-m);
        float e6 = ex2f(lv[6]-m), e7 = ex2f(lv[7]-m);
        float e8 = ex2f(lv[8]-m), e9 = ex2f(lv[9]-m);
        const float s = (((e0+e1)+(e2+e3)) + ((e4+e5)+(e6+e7))) + (e8+e9);
        sh->mrs[o*CC + c] = make_float2(m, rcpf(s));
    }
    __syncthreads();

    /* ---- sweep 2: rr, accumulate (loads hoisted ahead of ex2) ---- */
    float2 mr[P]; float av[P];
#pragma unroll
    for (int lp = 0; lp < P; lp++){
        mr[lp] = sh->mrs[lp*CC + c];
        av[lp] = sh->act[(gpt0+lp)*CC + c];
    }
#pragma unroll
    for (int lp = 0; lp < P; lp++){
        const float rr = ex2f(lg[lp] - mr[lp].x) * mr[lp].y;
        const float rp = rr * av[lp];
        S0 += rp;
        const u64 rk = pk2(rp, rp);
#pragma unroll
        for (int p = 0; p < 2; p++)
#pragma unroll
        for (int k = 0; k < 4; k++){
            const u64 ru = mul2(rk, u[lp][p][k]);
            S1[p][k] = add2(S1[p][k], ru);
            S2[p][k] = fma2(ru, u[lp][p][k], S2[p][k]);
        }
    }
}

/* soft pass (iterations 1 and 2), identical to round-8 structure */
__device__ __forceinline__ void stats_pass_soft(
    const float* __restrict__ pose_blk, Shm* sh,
    const u64 wpk[4][4], int c, int o, float* gp)
{
    u64 A2[2][4], nMU[2][4];
    const float C0 = sh->C0[o];
#pragma unroll
    for (int p = 0; p < 2; p++)
#pragma unroll
    for (int k = 0; k < 4; k++){
        A2[p][k]  = sh->A2pk[o*8 + p*4 + k];
        nMU[p][k] = sh->Mpk [o*8 + p*4 + k];
    }

    u64 S1[2][4], S2[2][4]; float S0 = 0.f;
#pragma unroll
    for (int p = 0; p < 2; p++)
#pragma unroll
    for (int k = 0; k < 4; k++){ S1[p][k] = 0ull; S2[p][k] = 0ull; }

    const int t = o*32 + c;
    const float4* pb4 = (const float4*)pose_blk;

    float4 pr0, pr1, pr2, pr3;
    if (t < G*CC){
        const float4* s = pb4 + (size_t)t*4;
        pr0 = s[0]; pr1 = s[1]; pr2 = s[2]; pr3 = s[3];
    }

    for (int g = 0; g < NGRP; g++){
        const int pts  = (g == NGRP-1) ? (HALF_S - (NGRP-1)*G) : G;   /* 8 or 2 */
        if (t < pts*CC){
            float2* sb2 = (float2*)&sh->sbuf[t*18];
            sb2[0] = make_float2(pr0.x, pr1.x);
            sb2[1] = make_float2(pr0.y, pr1.y);
            sb2[2] = make_float2(pr0.z, pr1.z);
            sb2[3] = make_float2(pr0.w, pr1.w);
            sb2[4] = make_float2(pr2.x, pr3.x);
            sb2[5] = make_float2(pr2.y, pr3.y);
            sb2[6] = make_float2(pr2.z, pr3.z);
            sb2[7] = make_float2(pr2.w, pr3.w);
        }
        __syncthreads();
        if (g < NGRP-1){
            const int npts = (g == NGRP-2) ? (HALF_S - (NGRP-1)*G) : G;
            if (t < npts*CC){
                const float4* s = pb4 + ((size_t)(g+1)*G*CC + t)*4;
                pr0 = s[0]; pr1 = s[1]; pr2 = s[2]; pr3 = s[3];
            }
        }

        if (pts == G){
            process_batch<4>(sh, g*G,     0, wpk, A2, nMU, C0, c, o, S0, S1, S2);
            process_batch<4>(sh, g*G + 4, 4, wpk, A2, nMU, C0, c, o, S0, S1, S2);
        } else {
            process_batch<2>(sh, g*G,     0, wpk, A2, nMU, C0, c, o, S0, S1, S2);
        }
    }

    float f[33];
#pragma unroll
    for (int p = 0; p < 2; p++)
#pragma unroll
    for (int k = 0; k < 4; k++){
        upk2(S1[p][k], f[p*8+k],    f[p*8+4+k]);
        upk2(S2[p][k], f[16+p*8+k], f[16+p*8+4+k]);
    }
    f[32] = S0;
#pragma unroll
    for (int off = 16; off > 0; off >>= 1){
#pragma unroll
        for (int i = 0; i < 33; i++)
            f[i] += __shfl_down_sync(0xffffffffu, f[i], off);
    }
    if (c == 0){
#pragma unroll
        for (int i = 0; i < 33; i++) gp[i] = f[i];
    }
}

/* ---------------- factored IT0: rr = 0.1 exactly, stats are a fixed
   polynomial in pose moments. Warps compute disjoint moment subsets, then
   each (c,o) thread contracts with its weights. Exact algebra vs direct. ---- */
__device__ __forceinline__ void stats_zero_fact(
    const float* __restrict__ pose_blk, Shm* sh,
    const u64 wpk[4][4], int c, int o, float* gp, int blk)
{
    float acc[10];
#pragma unroll
    for (int i = 0; i < 10; i++) acc[i] = 0.f;

    const int t = o*32 + c;
    const float4* pb4 = (const float4*)pose_blk;

    float4 pr0, pr1, pr2, pr3;
    if (t < G*CC){
        const float4* s = pb4 + (size_t)t*4;
        pr0 = s[0]; pr1 = s[1]; pr2 = s[2]; pr3 = s[3];
    }

    for (int g = 0; g < NGRP; g++){
        const int pts = (g == NGRP-1) ? (HALF_S - (NGRP-1)*G) : G;
        if (t < pts*CC){
            float2* sb2 = (float2*)&sh->sbuf[t*18];
            sb2[0] = make_float2(pr0.x, pr1.x);
            sb2[1] = make_float2(pr0.y, pr1.y);
            sb2[2] = make_float2(pr0.z, pr1.z);
            sb2[3] = make_float2(pr0.w, pr1.w);
            sb2[4] = make_float2(pr2.x, pr3.x);
            sb2[5] = make_float2(pr2.y, pr3.y);
            sb2[6] = make_float2(pr2.z, pr3.z);
            sb2[7] = make_float2(pr2.w, pr3.w);
        }
        __syncthreads();
        if (g < NGRP-1){
            const int npts = (g == NGRP-2) ? (HALF_S - (NGRP-1)*G) : G;
            if (t < npts*CC){
                const float4* s = pb4 + ((size_t)(g+1)*G*CC + t)*4;
                pr0 = s[0]; pr1 = s[1]; pr2 = s[2]; pr3 = s[3];
            }
        }

        /* sbuf row layout: float2 slot j = {p[0][j], p[1][j]}, slot 4+j = {p[2][j], p[3][j]} */
        for (int lp = 0; lp < pts; lp++){
            const float a = sh->act[(g*G + lp)*CC + c];
            const float2* q2 = (const float2*)(sh->sbuf) + ((size_t)lp*CC + c)*9;
            if (o < 4){
                /* Mpp[i=o][t] : t enumerates (j<=j') */
                const int bs = (o >> 1) << 2;
                const float2 a0 = q2[bs], a1 = q2[bs+1], a2 = q2[bs+2], a3 = q2[bs+3];
                const float p0 = (o & 1) ? a0.y : a0.x;
                const float p1 = (o & 1) ? a1.y : a1.x;
                const float p2 = (o & 1) ? a2.y : a2.x;
                const float p3 = (o & 1) ? a3.y : a3.x;
                const float t0 = a*p0, t1 = a*p1, t2 = a*p2, t3 = a*p3;
                acc[0]=fmaf(t0,p0,acc[0]); acc[1]=fmaf(t0,p1,acc[1]);
                acc[2]=fmaf(t0,p2,acc[2]); acc[3]=fmaf(t0,p3,acc[3]);
                acc[4]=fmaf(t1,p1,acc[4]); acc[5]=fmaf(t1,p2,acc[5]);
                acc[6]=fmaf(t1,p3,acc[6]); acc[7]=fmaf(t2,p2,acc[7]);
                acc[8]=fmaf(t2,p3,acc[8]); acc[9]=fmaf(t3,p3,acc[9]);
            } else if (o < 6){
                /* Mp rows (o-4)*2 and (o-4)*2+1 */
                const int bs = (o == 5) ? 4 : 0;
                const float2 a0 = q2[bs], a1 = q2[bs+1], a2 = q2[bs+2], a3 = q2[bs+3];
                acc[0]=fmaf(a,a0.x,acc[0]); acc[1]=fmaf(a,a1.x,acc[1]);
                acc[2]=fmaf(a,a2.x,acc[2]); acc[3]=fmaf(a,a3.x,acc[3]);
                acc[4]=fmaf(a,a0.y,acc[4]); acc[5]=fmaf(a,a1.y,acc[5]);
                acc[6]=fmaf(a,a2.y,acc[6]); acc[7]=fmaf(a,a3.y,acc[7]);
            } else if (o == 6){
                float ow, oh; upk2(sh->offs[g*G+lp], ow, oh);
                acc[0] += a;
                acc[1] = fmaf(a, ow, acc[1]);
                acc[2] = fmaf(a, oh, acc[2]);
                acc[3] = fmaf(a*ow, ow, acc[3]);
                acc[4] = fmaf(a*oh, oh, acc[4]);
            } else if (o == 7){
                float ow, oh; upk2(sh->offs[g*G+lp], ow, oh);
                const float aw = a*ow;
                const float2 a0 = q2[0], a1 = q2[1], a2 = q2[2], a3 = q2[3];
                acc[0]=fmaf(aw,a0.x,acc[0]); acc[1]=fmaf(aw,a1.x,acc[1]);
                acc[2]=fmaf(aw,a2.x,acc[2]); acc[3]=fmaf(aw,a3.x,acc[3]);
            } else if (o == 8){
                float ow, oh; upk2(sh->offs[g*G+lp], ow, oh);
                const float ah = a*oh;
                const float2 a0 = q2[0], a1 = q2[1], a2 = q2[2], a3 = q2[3];
                acc[0]=fmaf(ah,a0.y,acc[0]); acc[1]=fmaf(ah,a1.y,acc[1]);
                acc[2]=fmaf(ah,a2.y,acc[2]); acc[3]=fmaf(ah,a3.y,acc[3]);
            }
        }
        __syncthreads();
    }

    /* publish moments: layout [stat][c] for coalescing */
    float* mst = g_mst[blk];
    if (o < 4){
#pragma unroll
        for (int s = 0; s < 10; s++) mst[(16 + o*10 + s)*CC + c] = acc[s];
    } else if (o == 4){
#pragma unroll
        for (int s = 0; s < 8; s++) mst[s*CC + c] = acc[s];
    } else if (o == 5){
#pragma unroll
        for (int s = 0; s < 8; s++) mst[(8+s)*CC + c] = acc[s];
    } else if (o == 6){
#pragma unroll
        for (int s = 0; s < 5; s++) mst[(56+s)*CC + c] = acc[s];
    } else if (o == 7){
#pragma unroll
        for (int s = 0; s < 4; s++) mst[(61+s)*CC + c] = acc[s];
    } else if (o == 8){
#pragma unroll
        for (int s = 0; s < 4; s++) mst[(65+s)*CC + c] = acc[s];
    }
    __syncthreads();   /* orders global writes for block-local readers */

    /* contraction per (c,o) */
    float wv[4][4];
#pragma unroll
    for (int j = 0; j < 4; j++)
#pragma unroll
    for (int k = 0; k < 4; k++){ float lo, hi; upk2(wpk[j][k], lo, hi); wv[j][k] = lo; (void)hi; }

    float Mp[16];
#pragma unroll
    for (int s = 0; s < 16; s++) Mp[s] = mst[s*CC + c];
    float Mpp[40];
#pragma unroll
    for (int s = 0; s < 40; s++) Mpp[s] = mst[(16+s)*CC + c];
    const float M0  = mst[56*CC + c];
    const float Mw  = mst[57*CC + c];
    const float Mh  = mst[58*CC + c];
    const float Mw2 = mst[59*CC + c];
    const float Mh2 = mst[60*CC + c];
    float Mwp[4], Mhp[4];
#pragma unroll
    for (int s = 0; s < 4; s++){ Mwp[s] = mst[(61+s)*CC + c]; Mhp[s] = mst[(65+s)*CC + c]; }

    float f[33];
    /* S1[d=(i,k)] = sum_j Mp[i][j] w[j][k]  (+ coord means) */
#pragma unroll
    for (int i = 0; i < 4; i++)
#pragma unroll
    for (int k = 0; k < 4; k++){
        float s = Mp[i*4+0]*wv[0][k];
        s = fmaf(Mp[i*4+1], wv[1][k], s);
        s = fmaf(Mp[i*4+2], wv[2][k], s);
        s = fmaf(Mp[i*4+3], wv[3][k], s);
        f[i*4+k] = s;
    }
    f[3] += Mw; f[7] += Mh;
    /* S2[d=(i,k)] = sum_{j<=j'} Mpp[i][t] * (w products) */
#pragma unroll
    for (int k = 0; k < 4; k++){
        float pr[10];
        pr[0] = wv[0][k]*wv[0][k];
        pr[1] = 2.f*wv[0][k]*wv[1][k];
        pr[2] = 2.f*wv[0][k]*wv[2][k];
        pr[3] = 2.f*wv[0][k]*wv[3][k];
        pr[4] = wv[1][k]*wv[1][k];
        pr[5] = 2.f*wv[1][k]*wv[2][k];
        pr[6] = 2.f*wv[1][k]*wv[3][k];
        pr[7] = wv[2][k]*wv[2][k];
        pr[8] = 2.f*wv[2][k]*wv[3][k];
        pr[9] = wv[3][k]*wv[3][k];
#pragma unroll
        for (int i = 0; i < 4; i++){
            const float* mp = Mpp + i*10;
            float s = mp[0]*pr[0];
#pragma unroll
            for (int tt = 1; tt < 10; tt++) s = fmaf(mp[tt], pr[tt], s);
            f[16 + i*4 + k] = s;
        }
    }
    /* coord cross + squared terms: d=3 -> (i=0,k=3), d=7 -> (i=1,k=3) */
    {
        float cw = Mwp[0]*wv[0][3];
        cw = fmaf(Mwp[1], wv[1][3], cw);
        cw = fmaf(Mwp[2], wv[2][3], cw);
        cw = fmaf(Mwp[3], wv[3][3], cw);
        f[16+3] += 2.f*cw + Mw2;
        float ch = Mhp[0]*wv[0][3];
        ch = fmaf(Mhp[1], wv[1][3], ch);
        ch = fmaf(Mhp[2], wv[2][3], ch);
        ch = fmaf(Mhp[3], wv[3][3], ch);
        f[16+7] += 2.f*ch + Mh2;
    }
    f[32] = 0.1f*M0;
#pragma unroll
    for (int s = 0; s < 32; s++) f[s] *= 0.1f;

#pragma unroll
    for (int off = 16; off > 0; off >>= 1){
#pragma unroll
        for (int i = 0; i < 33; i++)
            f[i] += __shfl_down_sync(0xffffffffu, f[i], off);
    }
    if (c == 0){
#pragma unroll
        for (int i = 0; i < 33; i++) gp[i] = f[i];
    }
}

__device__ __forceinline__ void block_finalize(
    int it, int b, int tid, Shm* sh,
    const float* __restrict__ beta_a, const float* __restrict__ beta_u,
    float* __restrict__ out)
{
    if (tid < 160){
        const int o = tid >> 4, d = tid & 15;
        const float* buf = g_part[it & 1];
        const float* gp0 = &buf[((0*BB + b)*OO + o)*33];
        const float* gp1 = &buf[((1*BB + b)*OO + o)*33];
        const float T1 = __ldcg(gp0 + d)      + __ldcg(gp1 + d);
        const float T2 = __ldcg(gp0 + 16 + d) + __ldcg(gp1 + 16 + d);
        const float S0 = __ldcg(gp0 + 32)     + __ldcg(gp1 + 32);
        const float mu_prev = (it == 0) ? 0.f : sh->Mu[o*16 + d];

        const double S0d = (double)S0;
        const double rsd = S0d + (double)EPSV;
        const double S1d = (double)T1 + (double)mu_prev * S0d;
        const double mud = S1d / rsd;
        const double e   = mud - (double)mu_prev;
        double varnum = (double)T2 - 2.0*e*(double)T1 + e*e*S0d;
        if (varnum < 0.0) varnum = 0.0;
        const double vard = varnum / rsd + (double)EPSV;

        const float mu   = (float)mud;
        const float var  = (float)vard;
        const float lvar = logf(var);
        const float iv   = 1.0f/var;
        const float rs   = (float)rsd;

        float r1 = lvar;
#pragma unroll
        for (int m = 8; m > 0; m >>= 1)
            r1 += __shfl_xor_sync(0xffffffffu, r1, m);

        const float cost     = rs * (16.0f*beta_u[o] + 0.5f*r1);
        const float inv_temp = 1.0f + (float)it;
        const float z        = inv_temp * (beta_a[o] - cost);
        const float actv     = 1.0f / (1.0f + expf(-z));

        if (it < 2){
            const int p = d >> 3, hi = (d >> 2) & 1, k = d & 3;
            ((float*)&sh->A2pk[o*8 + p*4 + k])[hi] = -0.5f*iv*LOG2E;
            ((float*)&sh->Mpk [o*8 + p*4 + k])[hi] = -mu;
            sh->Mu[o*16 + d] = mu;
            if (d == 0)
                sh->C0[o] = (logf(actv + EPSV) - 0.5f*(16.0f*LN2PI + r1)) * LOG2E;
        } else {
            out[(b*OO + o)*16 + d] = mu;
            if (d == 0) out[BB*OO*16 + b*OO + o] = actv;
        }
    }
    __syncthreads();
}

__global__ __launch_bounds__(320)
void fccaps_kernel(const float* __restrict__ pose,
                   const float* __restrict__ act,
                   const float* __restrict__ wmat,
                   const float* __restrict__ beta_a,
                   const float* __restrict__ beta_u,
                   float* __restrict__ out)
{
    __shared__ Shm sh;

    const int c   = threadIdx.x;
    const int o   = threadIdx.y;
    const int tid = o*32 + c;
    const int b    = blockIdx.x >> 1;
    const int half = blockIdx.x & 1;
    const int s0   = half * HALF_S;

    for (int i = tid; i < HALF_S*CC; i += 320)
        sh.act[i] = act[(size_t)b*NN + (size_t)s0*CC + i];
    if (tid < HALF_S){
        const int s = s0 + tid;
        sh.offs[tid] = pk2(((s % WW) + 0.5f)*(1.0f/WW),
                           ((s / WW) + 0.5f)*(1.0f/HH));
    }
    if (tid == 0) sh.e0 = *(volatile unsigned*)&g_epoch;

    u64 wpk[4][4];
#pragma unroll
    for (int j = 0; j < 4; j++)
#pragma unroll
    for (int k = 0; k < 4; k++){
        const float wv = wmat[((size_t)(c*OO + o))*16 + j*4 + k];
        wpk[j][k] = pk2(wv, wv);
    }
    __syncthreads();
    const unsigned e0 = sh.e0;

    const float* pose_blk = pose + ((size_t)b*NN + (size_t)s0*CC)*16;
    const size_t gpi = (((size_t)half*BB + b)*OO + o)*33;

    stats_zero_fact(pose_blk, &sh, wpk, c, o, &g_part[0][gpi], blockIdx.x);
    grid_barrier(e0 + 1);
    block_finalize(0, b, tid, &sh, beta_a, beta_u, out);

    stats_pass_soft(pose_blk, &sh, wpk, c, o, &g_part[1][gpi]);
    grid_barrier(e0 + 2);
    block_finalize(1, b, tid, &sh, beta_a, beta_u, out);

    stats_pass_soft(pose_blk, &sh, wpk, c, o, &g_part[0][gpi]);
    grid_barrier(e0 + 3);
    if (half == 0)
        block_finalize(2, b, tid, &sh, beta_a, beta_u, out);
}

extern "C" void kernel_launch(void* const* d_in, const int* in_sizes, int n_in,
                              void* d_out, int out_size)
{
    const float* pose = (const float*)d_in[0];  // (B,H,W,C,16)
    const float* actv = (const float*)d_in[1];  // (B,H,W,C,1)
    const float* wmat = (const float*)d_in[2];  // (C,O,4,4)
    const float* ba   = (const float*)d_in[3];  // (1,1,O,1)
    const float* bu   = (const float*)d_in[4];  // (1,1,O,1)
    float* out = (float*)d_out;                 // pose(B,O,16) then act(B,O)

    dim3 blk(32, 10);
    fccaps_kernel<<<NBLK, blk>>>(pose, actv, wmat, ba, bu, out);
}